// round 11
// baseline (speedup 1.0000x reference)
#include <cuda_runtime.h>
#include <cuda_fp16.h>
#include <cstdint>

// Problem constants (fixed by the reference)
#define CIN   64
#define COUT  64
#define KOFF  27
#define MPAIR 131072
#define NOUT  262144
#define NIN   262144
#define EPS   1e-5f
#define SLOPE 0.01f

// conv tiling: block = 256 threads (8 warps); warp = 8 pairs/step;
// block = 64 pairs/step x 16 steps = 1024 pairs. grid = (128, 27).
#define BLK_PAIRS 1024
#define STEPS     16

// smem: two staging buffers of 64 rows x 68 floats (272B row stride)
#define BUF_STRIDE 68
#define BUF_ROWS   64
#define BUF_FLOATS (BUF_ROWS * BUF_STRIDE)
#define SMEM_BYTES (2 * BUF_FLOATS * 4)     // 34816

// Pre-converted fp16 operands (device scratch; no runtime allocation)
// feats row layout (32 uints = 64 fp16): uint index p = a*8 + kt*2 + h
// holds half2( feats[ci], feats[ci+1] ), ci = kt*16 + 2a + 8h.
__device__ uint32_t g_featsH[NIN * 32];          // 33.5 MB
// W fragments per k: lane-major, lane (r,a) owns 64 uints:
// index mt*16 + kt*4 + j, j bit0 = cout+8, bit1 = cin+8:
//   half2( W[ci][co], W[ci+1][co] ), ci = 16kt+2a+8*(j>>1), co = 16mt+r+8*(j&1)
__device__ uint32_t g_WH[KOFF * 2048];           // 216 KB

// BN statistics scratch
__device__ float g_sum[COUT];
__device__ float g_sumsq[COUT];

__device__ __forceinline__ uint32_t smem_u32(const void* p) {
    uint32_t a;
    asm("{ .reg .u64 t; cvta.to.shared.u64 t, %1; cvt.u32.u64 %0, t; }"
        : "=r"(a) : "l"(p));
    return a;
}

// ---------------------------------------------------------------------------
// Kernel 0: fused zero(out) + pre-convert feats/W to fp16 fragment layouts.
// grid = 8192 x 256.
// ---------------------------------------------------------------------------
__global__ void __launch_bounds__(256)
precvt_kernel(const float* __restrict__ feats, const float* __restrict__ W,
              float4* __restrict__ out4)
{
    const int tid = threadIdx.x;
    const int t4  = blockIdx.x * 256 + tid;        // 0 .. 2,097,151

    // zero the 67 MB accumulator (2 float4s per thread)
    const float4 z = make_float4(0.f, 0.f, 0.f, 0.f);
    out4[2 * (size_t)t4]     = z;
    out4[2 * (size_t)t4 + 1] = z;
    if (blockIdx.x == 0 && tid < COUT) {
        g_sum[tid]   = 0.f;
        g_sumsq[tid] = 0.f;
    }

    // feats packing (B-fragment layout)
    const int row = t4 >> 3;
    const int p0  = (t4 & 7) << 2;                 // first of 4 uint slots
    const float* src = feats + (size_t)row * CIN;
    uint32_t v[4];
    #pragma unroll
    for (int i = 0; i < 4; i++) {
        const int up = p0 + i;
        const int a  = up >> 3;
        const int kt = (up >> 1) & 3;
        const int h  = up & 1;
        const int ci = kt * 16 + 2 * a + 8 * h;
        __half2 hv = __floats2half2_rn(src[ci], src[ci + 1]);
        v[i] = *reinterpret_cast<uint32_t*>(&hv);
    }
    *reinterpret_cast<uint4*>(g_featsH + (size_t)row * 32 + p0) =
        make_uint4(v[0], v[1], v[2], v[3]);

    // W packing (A-fragment, lane-stationary layout)
    if (blockIdx.x < KOFF) {
        const float* Wk = W + blockIdx.x * (CIN * COUT);
        uint32_t* dst = g_WH + blockIdx.x * 2048;
        for (int i = tid; i < 2048; i += 256) {
            const int lane = i >> 6;
            const int rem  = i & 63;
            const int mt   = rem >> 4;
            const int kt   = (rem >> 2) & 3;
            const int j    = rem & 3;
            const int r    = lane >> 2;
            const int a    = lane & 3;
            const int ci   = 16 * kt + 2 * a + 8 * (j >> 1);
            const int co   = 16 * mt + r + 8 * (j & 1);
            __half2 hv = __floats2half2_rn(Wk[ci * COUT + co],
                                           Wk[(ci + 1) * COUT + co]);
            dst[i] = *reinterpret_cast<uint32_t*>(&hv);
        }
    }
}

// ---------------------------------------------------------------------------
// Kernel 1: sparse conv, register-stationary W (A operand), feats as B.
// D[cout=64, pair=8] per warp-step via 16x mma m16n8k16 (f32 acc).
// No LDS in the hot loop. Scatter via cp.reduce.async.bulk, double buffered.
// Maps loaded with __ldcs (evict-first) to protect the hot L2 set
// (featsH 33.5MB + out 67MB). Small blocks (1024 pairs) keep the final
// wave short so LTS stays saturated.
// grid = (MPAIR/1024, KOFF); block = 256.
// ---------------------------------------------------------------------------
__global__ void __launch_bounds__(256, 2)
conv_kernel(const int* __restrict__ in_map,
            const int* __restrict__ out_map,
            float*     __restrict__ out)
{
    extern __shared__ float bufs[];

    const int k    = blockIdx.y;
    const int tid  = threadIdx.x;
    const int warp = tid >> 5;
    const int lane = tid & 31;
    const int r = lane >> 2;   // 0..7 (fragment group id)
    const int a = lane & 3;    // 0..3

    const int* im = in_map  + k * MPAIR;
    const int* om = out_map + k * MPAIR;

    // ---- stationary W fragments: 64 uints per lane, loaded once ----
    uint32_t Wf[64];
    {
        const uint4* wp = reinterpret_cast<const uint4*>(
            g_WH + k * 2048 + lane * 64);
        #pragma unroll
        for (int i = 0; i < 16; i++)
            *reinterpret_cast<uint4*>(Wf + 4 * i) = wp[i];
    }

    const int base_w = blockIdx.x * BLK_PAIRS + warp * 8;
    float* wbase = bufs + warp * 8 * BUF_STRIDE;

    // ---- prologue: gather step 0 ----
    uint32_t B0[8];
    int orow = 0;
    {
        const uint4* rp = reinterpret_cast<const uint4*>(
            g_featsH + (size_t)__ldcs(im + base_w + r) * 32 + a * 8);
        *reinterpret_cast<uint4*>(B0)     = rp[0];
        *reinterpret_cast<uint4*>(B0 + 4) = rp[1];
        if (lane < 8) orow = __ldcs(om + base_w + lane);
    }

    #pragma unroll 2
    for (int s = 0; s < STEPS; s++) {
        // ---- prefetch step s+1 ----
        uint32_t Bn[8];
        int orow_n = 0;
        if (s < STEPS - 1) {
            const int basen = base_w + (s + 1) * 64;
            if (lane < 8) orow_n = __ldcs(om + basen + lane);
            const uint4* rp = reinterpret_cast<const uint4*>(
                g_featsH + (size_t)__ldcs(im + basen + r) * 32 + a * 8);
            *reinterpret_cast<uint4*>(Bn)     = rp[0];
            *reinterpret_cast<uint4*>(Bn + 4) = rp[1];
        }

        // ---- MMA: D[64 cout, 8 pairs], K=64 ----
        float acc[4][4];
        #pragma unroll
        for (int mt = 0; mt < 4; mt++)
            #pragma unroll
            for (int q = 0; q < 4; q++) acc[mt][q] = 0.f;

        #pragma unroll
        for (int kt = 0; kt < 4; kt++) {
            const uint32_t b0 = B0[2 * kt];
            const uint32_t b1 = B0[2 * kt + 1];
            #pragma unroll
            for (int mt = 0; mt < 4; mt++) {
                const uint32_t* w = Wf + mt * 16 + kt * 4;
                asm volatile(
                    "mma.sync.aligned.m16n8k16.row.col.f32.f16.f16.f32 "
                    "{%0,%1,%2,%3}, {%4,%5,%6,%7}, {%8,%9}, {%0,%1,%2,%3};"
                    : "+f"(acc[mt][0]), "+f"(acc[mt][1]),
                      "+f"(acc[mt][2]), "+f"(acc[mt][3])
                    : "r"(w[0]), "r"(w[1]), "r"(w[2]), "r"(w[3]),
                      "r"(b0), "r"(b1));
            }
        }

        // ---- epilogue: stage 8 rows (pair-major), bulk reduce-add ----
        float* wbuf = wbase + (s & 1) * BUF_FLOATS;

        // the group that used THIS buffer (2 steps ago) must be read out
        asm volatile("cp.async.bulk.wait_group.read 1;" ::: "memory");
        __syncwarp();

        // D frag: lane(r,a), mt: c0=D[16mt+r][2a], c1=D[16mt+r][2a+1],
        //                        c2=D[16mt+r+8][2a], c3=D[16mt+r+8][2a+1]
        // staging row = pair (0..7), columns = cout
        #pragma unroll
        for (int mt = 0; mt < 4; mt++) {
            wbuf[(2 * a)     * BUF_STRIDE + 16 * mt + r]     = acc[mt][0];
            wbuf[(2 * a + 1) * BUF_STRIDE + 16 * mt + r]     = acc[mt][1];
            wbuf[(2 * a)     * BUF_STRIDE + 16 * mt + r + 8] = acc[mt][2];
            wbuf[(2 * a + 1) * BUF_STRIDE + 16 * mt + r + 8] = acc[mt][3];
        }
        __syncwarp();
        asm volatile("fence.proxy.async.shared::cta;" ::: "memory");

        if (lane < 8) {
            float* dst = out + (size_t)orow * COUT;
            uint32_t src = smem_u32(wbuf + lane * BUF_STRIDE);
            asm volatile(
                "cp.reduce.async.bulk.global.shared::cta.bulk_group.add.f32 "
                "[%0], [%1], %2;"
                :: "l"(dst), "r"(src), "r"(256) : "memory");
        }
        asm volatile("cp.async.bulk.commit_group;" ::: "memory");

        // rotate pipeline registers
        orow = orow_n;
        #pragma unroll
        for (int i = 0; i < 8; i++) B0[i] = Bn[i];
    }

    // all reduce writes must complete before kernel end
    asm volatile("cp.async.bulk.wait_group 0;" ::: "memory");
}

// ---------------------------------------------------------------------------
// Kernel 2: per-column sum / sumsq, float4 loads.
// grid = 512 blocks x 256 threads; 512 rows per block (32 per thread).
// ---------------------------------------------------------------------------
__global__ void stats_kernel(const float4* __restrict__ out4) {
    __shared__ float4 ssum[256], ssq[256];
    const int tid = threadIdx.x;
    const int c4  = tid & 15;
    const int q   = tid >> 4;
    const int rowbase = blockIdx.x * 512;

    float4 s  = make_float4(0.f, 0.f, 0.f, 0.f);
    float4 s2 = make_float4(0.f, 0.f, 0.f, 0.f);
    #pragma unroll 8
    for (int i = 0; i < 32; i++) {
        const float4 v = out4[(size_t)(rowbase + i * 16 + q) * 16 + c4];
        s.x += v.x; s.y += v.y; s.z += v.z; s.w += v.w;
        s2.x += v.x * v.x; s2.y += v.y * v.y;
        s2.z += v.z * v.z; s2.w += v.w * v.w;
    }
    ssum[tid] = s; ssq[tid] = s2;
    __syncthreads();
    if (q == 0) {
        float4 ts  = make_float4(0.f, 0.f, 0.f, 0.f);
        float4 ts2 = make_float4(0.f, 0.f, 0.f, 0.f);
        #pragma unroll
        for (int g = 0; g < 16; g++) {
            const float4 u  = ssum[g * 16 + c4];
            const float4 u2 = ssq[g * 16 + c4];
            ts.x += u.x; ts.y += u.y; ts.z += u.z; ts.w += u.w;
            ts2.x += u2.x; ts2.y += u2.y; ts2.z += u2.z; ts2.w += u2.w;
        }
        atomicAdd(&g_sum[c4 * 4 + 0], ts.x);
        atomicAdd(&g_sum[c4 * 4 + 1], ts.y);
        atomicAdd(&g_sum[c4 * 4 + 2], ts.z);
        atomicAdd(&g_sum[c4 * 4 + 3], ts.w);
        atomicAdd(&g_sumsq[c4 * 4 + 0], ts2.x);
        atomicAdd(&g_sumsq[c4 * 4 + 1], ts2.y);
        atomicAdd(&g_sumsq[c4 * 4 + 2], ts2.z);
        atomicAdd(&g_sumsq[c4 * 4 + 3], ts2.w);
    }
}

// ---------------------------------------------------------------------------
// Kernel 3: BN affine + LeakyReLU, in place, 2 independent float4 per thread
// for load-latency ILP. grid = 8192 x 256.
// ---------------------------------------------------------------------------
__global__ void apply_kernel(float* __restrict__ out,
                             const float* __restrict__ gamma,
                             const float* __restrict__ beta)
{
    __shared__ float sc[COUT], bi[COUT];
    const int tid = threadIdx.x;
    if (tid < COUT) {
        const float inv_n = 1.f / (float)NOUT;
        float mean = g_sum[tid] * inv_n;
        float var  = g_sumsq[tid] * inv_n - mean * mean;
        float s = gamma[tid] * rsqrtf(var + EPS);
        sc[tid] = s;
        bi[tid] = beta[tid] - mean * s;
    }
    __syncthreads();

    float4* o4 = reinterpret_cast<float4*>(out);
    const int i0 = blockIdx.x * 512 + tid;           // two float4s, 256 apart
    float4 v0 = o4[i0];
    float4 v1 = o4[i0 + 256];
    const int c0 = (i0 & 15) * 4;
    const int c1 = ((i0 + 256) & 15) * 4;

    float y;
    y = v0.x * sc[c0 + 0] + bi[c0 + 0]; v0.x = (y >= 0.f) ? y : SLOPE * y;
    y = v0.y * sc[c0 + 1] + bi[c0 + 1]; v0.y = (y >= 0.f) ? y : SLOPE * y;
    y = v0.z * sc[c0 + 2] + bi[c0 + 2]; v0.z = (y >= 0.f) ? y : SLOPE * y;
    y = v0.w * sc[c0 + 3] + bi[c0 + 3]; v0.w = (y >= 0.f) ? y : SLOPE * y;
    y = v1.x * sc[c1 + 0] + bi[c1 + 0]; v1.x = (y >= 0.f) ? y : SLOPE * y;
    y = v1.y * sc[c1 + 1] + bi[c1 + 1]; v1.y = (y >= 0.f) ? y : SLOPE * y;
    y = v1.z * sc[c1 + 2] + bi[c1 + 2]; v1.z = (y >= 0.f) ? y : SLOPE * y;
    y = v1.w * sc[c1 + 3] + bi[c1 + 3]; v1.w = (y >= 0.f) ? y : SLOPE * y;

    o4[i0]       = v0;
    o4[i0 + 256] = v1;
}

// ---------------------------------------------------------------------------
// Launch
// inputs (metadata order): feats f32[N_IN*64], W f32[27*64*64], gamma f32[64],
//   beta f32[64], in_map i32[27*M], out_map i32[27*M], num_out i32[1]
// ---------------------------------------------------------------------------
extern "C" void kernel_launch(void* const* d_in, const int* in_sizes, int n_in,
                              void* d_out, int out_size)
{
    const float* feats   = (const float*)d_in[0];
    const float* W       = (const float*)d_in[1];
    const float* gamma   = (const float*)d_in[2];
    const float* beta    = (const float*)d_in[3];
    const int*   in_map  = (const int*)d_in[4];
    const int*   out_map = (const int*)d_in[5];
    float*       out     = (float*)d_out;

    precvt_kernel<<<8192, 256>>>(feats, W, reinterpret_cast<float4*>(out));

    cudaFuncSetAttribute(conv_kernel,
                         cudaFuncAttributeMaxDynamicSharedMemorySize,
                         SMEM_BYTES);
    dim3 grid(MPAIR / BLK_PAIRS, KOFF);          // 128 x 27
    conv_kernel<<<grid, 256, SMEM_BYTES>>>(in_map, out_map, out);

    stats_kernel<<<512, 256>>>(reinterpret_cast<const float4*>(out));

    apply_kernel<<<8192, 256>>>(out, gamma, beta);
}

// round 12
// speedup vs baseline: 1.0345x; 1.0345x over previous
#include <cuda_runtime.h>
#include <cuda_fp16.h>
#include <cstdint>

// Problem constants (fixed by the reference)
#define CIN   64
#define COUT  64
#define KOFF  27
#define MPAIR 131072
#define NOUT  262144
#define NIN   262144
#define EPS   1e-5f
#define SLOPE 0.01f

// conv tiling: block = 256 threads (8 warps); warp = 8 pairs/step;
// block = 64 pairs/step x 32 steps = 2048 pairs. grid = (64, 27).
#define BLK_PAIRS 2048
#define STEPS     32

// smem: THREE staging buffers of 64 rows x 68 floats (272B row stride)
#define BUF_STRIDE 68
#define BUF_ROWS   64
#define BUF_FLOATS (BUF_ROWS * BUF_STRIDE)
#define NBUF       3
#define SMEM_BYTES (NBUF * BUF_FLOATS * 4)     // 52224

// Pre-converted fp16 operands (device scratch; no runtime allocation)
// feats row layout (32 uints = 64 fp16): uint index p = a*8 + kt*2 + h
// holds half2( feats[ci], feats[ci+1] ), ci = kt*16 + 2a + 8h.
__device__ uint32_t g_featsH[NIN * 32];          // 33.5 MB
// W fragments per k: lane-major, lane (r,a) owns 64 uints:
// index mt*16 + kt*4 + j, j bit0 = cout+8, bit1 = cin+8:
//   half2( W[ci][co], W[ci+1][co] ), ci = 16kt+2a+8*(j>>1), co = 16mt+r+8*(j&1)
__device__ uint32_t g_WH[KOFF * 2048];           // 216 KB

// BN statistics scratch
__device__ float g_sum[COUT];
__device__ float g_sumsq[COUT];

__device__ __forceinline__ uint32_t smem_u32(const void* p) {
    uint32_t a;
    asm("{ .reg .u64 t; cvta.to.shared.u64 t, %1; cvt.u32.u64 %0, t; }"
        : "=r"(a) : "l"(p));
    return a;
}

// ---------------------------------------------------------------------------
// Kernel 0: fused zero(out) + pre-convert feats/W to fp16 fragment layouts.
// grid = 8192 x 256.
// ---------------------------------------------------------------------------
__global__ void __launch_bounds__(256)
precvt_kernel(const float* __restrict__ feats, const float* __restrict__ W,
              float4* __restrict__ out4)
{
    const int tid = threadIdx.x;
    const int t4  = blockIdx.x * 256 + tid;        // 0 .. 2,097,151

    // zero the 67 MB accumulator (2 float4s per thread)
    const float4 z = make_float4(0.f, 0.f, 0.f, 0.f);
    out4[2 * (size_t)t4]     = z;
    out4[2 * (size_t)t4 + 1] = z;
    if (blockIdx.x == 0 && tid < COUT) {
        g_sum[tid]   = 0.f;
        g_sumsq[tid] = 0.f;
    }

    // feats packing (B-fragment layout)
    const int row = t4 >> 3;
    const int p0  = (t4 & 7) << 2;                 // first of 4 uint slots
    const float* src = feats + (size_t)row * CIN;
    uint32_t v[4];
    #pragma unroll
    for (int i = 0; i < 4; i++) {
        const int up = p0 + i;
        const int a  = up >> 3;
        const int kt = (up >> 1) & 3;
        const int h  = up & 1;
        const int ci = kt * 16 + 2 * a + 8 * h;
        __half2 hv = __floats2half2_rn(src[ci], src[ci + 1]);
        v[i] = *reinterpret_cast<uint32_t*>(&hv);
    }
    *reinterpret_cast<uint4*>(g_featsH + (size_t)row * 32 + p0) =
        make_uint4(v[0], v[1], v[2], v[3]);

    // W packing (A-fragment, lane-stationary layout)
    if (blockIdx.x < KOFF) {
        const float* Wk = W + blockIdx.x * (CIN * COUT);
        uint32_t* dst = g_WH + blockIdx.x * 2048;
        for (int i = tid; i < 2048; i += 256) {
            const int lane = i >> 6;
            const int rem  = i & 63;
            const int mt   = rem >> 4;
            const int kt   = (rem >> 2) & 3;
            const int j    = rem & 3;
            const int r    = lane >> 2;
            const int a    = lane & 3;
            const int ci   = 16 * kt + 2 * a + 8 * (j >> 1);
            const int co   = 16 * mt + r + 8 * (j & 1);
            __half2 hv = __floats2half2_rn(Wk[ci * COUT + co],
                                           Wk[(ci + 1) * COUT + co]);
            dst[i] = *reinterpret_cast<uint32_t*>(&hv);
        }
    }
}

// ---------------------------------------------------------------------------
// Kernel 1: sparse conv, register-stationary W (A operand), feats as B.
// D[cout=64, pair=8] per warp-step via 16x mma m16n8k16 (f32 acc).
// No LDS in the hot loop. Scatter via cp.reduce.async.bulk, TRIPLE buffered
// (wait_group.read 2) so transient LTS backlog doesn't stall the warp.
// grid = (MPAIR/2048, KOFF); block = 256.
// ---------------------------------------------------------------------------
__global__ void __launch_bounds__(256, 2)
conv_kernel(const int* __restrict__ in_map,
            const int* __restrict__ out_map,
            float*     __restrict__ out)
{
    extern __shared__ float bufs[];

    const int k    = blockIdx.y;
    const int tid  = threadIdx.x;
    const int warp = tid >> 5;
    const int lane = tid & 31;
    const int r = lane >> 2;   // 0..7 (fragment group id)
    const int a = lane & 3;    // 0..3

    const int* im = in_map  + k * MPAIR;
    const int* om = out_map + k * MPAIR;

    // ---- stationary W fragments: 64 uints per lane, loaded once ----
    uint32_t Wf[64];
    {
        const uint4* wp = reinterpret_cast<const uint4*>(
            g_WH + k * 2048 + lane * 64);
        #pragma unroll
        for (int i = 0; i < 16; i++)
            *reinterpret_cast<uint4*>(Wf + 4 * i) = wp[i];
    }

    const int base_w = blockIdx.x * BLK_PAIRS + warp * 8;
    float* wbase = bufs + warp * 8 * BUF_STRIDE;

    // ---- prologue: gather step 0 ----
    uint32_t B0[8];
    int orow = 0;
    {
        const uint4* rp = reinterpret_cast<const uint4*>(
            g_featsH + (size_t)im[base_w + r] * 32 + a * 8);
        *reinterpret_cast<uint4*>(B0)     = rp[0];
        *reinterpret_cast<uint4*>(B0 + 4) = rp[1];
        if (lane < 8) orow = om[base_w + lane];
    }

    int bufsel = 0;
    #pragma unroll 2
    for (int s = 0; s < STEPS; s++) {
        // ---- prefetch step s+1 ----
        uint32_t Bn[8];
        int orow_n = 0;
        if (s < STEPS - 1) {
            const int basen = base_w + (s + 1) * 64;
            if (lane < 8) orow_n = om[basen + lane];
            const uint4* rp = reinterpret_cast<const uint4*>(
                g_featsH + (size_t)im[basen + r] * 32 + a * 8);
            *reinterpret_cast<uint4*>(Bn)     = rp[0];
            *reinterpret_cast<uint4*>(Bn + 4) = rp[1];
        }

        // ---- MMA: D[64 cout, 8 pairs], K=64 ----
        float acc[4][4];
        #pragma unroll
        for (int mt = 0; mt < 4; mt++)
            #pragma unroll
            for (int q = 0; q < 4; q++) acc[mt][q] = 0.f;

        #pragma unroll
        for (int kt = 0; kt < 4; kt++) {
            const uint32_t b0 = B0[2 * kt];
            const uint32_t b1 = B0[2 * kt + 1];
            #pragma unroll
            for (int mt = 0; mt < 4; mt++) {
                const uint32_t* w = Wf + mt * 16 + kt * 4;
                asm volatile(
                    "mma.sync.aligned.m16n8k16.row.col.f32.f16.f16.f32 "
                    "{%0,%1,%2,%3}, {%4,%5,%6,%7}, {%8,%9}, {%0,%1,%2,%3};"
                    : "+f"(acc[mt][0]), "+f"(acc[mt][1]),
                      "+f"(acc[mt][2]), "+f"(acc[mt][3])
                    : "r"(w[0]), "r"(w[1]), "r"(w[2]), "r"(w[3]),
                      "r"(b0), "r"(b1));
            }
        }

        // ---- epilogue: stage 8 rows (pair-major), bulk reduce-add ----
        float* wbuf = wbase + bufsel * BUF_FLOATS;

        // the group that used THIS buffer (3 steps ago) must be read out
        asm volatile("cp.async.bulk.wait_group.read 2;" ::: "memory");
        __syncwarp();

        // D frag: lane(r,a), mt: c0=D[16mt+r][2a], c1=D[16mt+r][2a+1],
        //                        c2=D[16mt+r+8][2a], c3=D[16mt+r+8][2a+1]
        // staging row = pair (0..7), columns = cout
        #pragma unroll
        for (int mt = 0; mt < 4; mt++) {
            wbuf[(2 * a)     * BUF_STRIDE + 16 * mt + r]     = acc[mt][0];
            wbuf[(2 * a + 1) * BUF_STRIDE + 16 * mt + r]     = acc[mt][1];
            wbuf[(2 * a)     * BUF_STRIDE + 16 * mt + r + 8] = acc[mt][2];
            wbuf[(2 * a + 1) * BUF_STRIDE + 16 * mt + r + 8] = acc[mt][3];
        }
        __syncwarp();
        asm volatile("fence.proxy.async.shared::cta;" ::: "memory");

        if (lane < 8) {
            float* dst = out + (size_t)orow * COUT;
            uint32_t src = smem_u32(wbuf + lane * BUF_STRIDE);
            asm volatile(
                "cp.reduce.async.bulk.global.shared::cta.bulk_group.add.f32 "
                "[%0], [%1], %2;"
                :: "l"(dst), "r"(src), "r"(256) : "memory");
        }
        asm volatile("cp.async.bulk.commit_group;" ::: "memory");

        // rotate pipeline registers / buffer selector
        orow = orow_n;
        bufsel = (bufsel == NBUF - 1) ? 0 : bufsel + 1;
        #pragma unroll
        for (int i = 0; i < 8; i++) B0[i] = Bn[i];
    }

    // all reduce writes must complete before kernel end
    asm volatile("cp.async.bulk.wait_group 0;" ::: "memory");
}

// ---------------------------------------------------------------------------
// Kernel 2: per-column sum / sumsq, float4 loads.
// grid = 512 blocks x 256 threads; 512 rows per block (32 per thread).
// ---------------------------------------------------------------------------
__global__ void stats_kernel(const float4* __restrict__ out4) {
    __shared__ float4 ssum[256], ssq[256];
    const int tid = threadIdx.x;
    const int c4  = tid & 15;
    const int q   = tid >> 4;
    const int rowbase = blockIdx.x * 512;

    float4 s  = make_float4(0.f, 0.f, 0.f, 0.f);
    float4 s2 = make_float4(0.f, 0.f, 0.f, 0.f);
    #pragma unroll 8
    for (int i = 0; i < 32; i++) {
        const float4 v = out4[(size_t)(rowbase + i * 16 + q) * 16 + c4];
        s.x += v.x; s.y += v.y; s.z += v.z; s.w += v.w;
        s2.x += v.x * v.x; s2.y += v.y * v.y;
        s2.z += v.z * v.z; s2.w += v.w * v.w;
    }
    ssum[tid] = s; ssq[tid] = s2;
    __syncthreads();
    if (q == 0) {
        float4 ts  = make_float4(0.f, 0.f, 0.f, 0.f);
        float4 ts2 = make_float4(0.f, 0.f, 0.f, 0.f);
        #pragma unroll
        for (int g = 0; g < 16; g++) {
            const float4 u  = ssum[g * 16 + c4];
            const float4 u2 = ssq[g * 16 + c4];
            ts.x += u.x; ts.y += u.y; ts.z += u.z; ts.w += u.w;
            ts2.x += u2.x; ts2.y += u2.y; ts2.z += u2.z; ts2.w += u2.w;
        }
        atomicAdd(&g_sum[c4 * 4 + 0], ts.x);
        atomicAdd(&g_sum[c4 * 4 + 1], ts.y);
        atomicAdd(&g_sum[c4 * 4 + 2], ts.z);
        atomicAdd(&g_sum[c4 * 4 + 3], ts.w);
        atomicAdd(&g_sumsq[c4 * 4 + 0], ts2.x);
        atomicAdd(&g_sumsq[c4 * 4 + 1], ts2.y);
        atomicAdd(&g_sumsq[c4 * 4 + 2], ts2.z);
        atomicAdd(&g_sumsq[c4 * 4 + 3], ts2.w);
    }
}

// ---------------------------------------------------------------------------
// Kernel 3: BN affine + LeakyReLU, in place, 2 independent float4 per thread
// for load-latency ILP. grid = 8192 x 256.
// ---------------------------------------------------------------------------
__global__ void apply_kernel(float* __restrict__ out,
                             const float* __restrict__ gamma,
                             const float* __restrict__ beta)
{
    __shared__ float sc[COUT], bi[COUT];
    const int tid = threadIdx.x;
    if (tid < COUT) {
        const float inv_n = 1.f / (float)NOUT;
        float mean = g_sum[tid] * inv_n;
        float var  = g_sumsq[tid] * inv_n - mean * mean;
        float s = gamma[tid] * rsqrtf(var + EPS);
        sc[tid] = s;
        bi[tid] = beta[tid] - mean * s;
    }
    __syncthreads();

    float4* o4 = reinterpret_cast<float4*>(out);
    const int i0 = blockIdx.x * 512 + tid;           // two float4s, 256 apart
    float4 v0 = o4[i0];
    float4 v1 = o4[i0 + 256];
    const int c0 = (i0 & 15) * 4;
    const int c1 = ((i0 + 256) & 15) * 4;

    float y;
    y = v0.x * sc[c0 + 0] + bi[c0 + 0]; v0.x = (y >= 0.f) ? y : SLOPE * y;
    y = v0.y * sc[c0 + 1] + bi[c0 + 1]; v0.y = (y >= 0.f) ? y : SLOPE * y;
    y = v0.z * sc[c0 + 2] + bi[c0 + 2]; v0.z = (y >= 0.f) ? y : SLOPE * y;
    y = v0.w * sc[c0 + 3] + bi[c0 + 3]; v0.w = (y >= 0.f) ? y : SLOPE * y;
    y = v1.x * sc[c1 + 0] + bi[c1 + 0]; v1.x = (y >= 0.f) ? y : SLOPE * y;
    y = v1.y * sc[c1 + 1] + bi[c1 + 1]; v1.y = (y >= 0.f) ? y : SLOPE * y;
    y = v1.z * sc[c1 + 2] + bi[c1 + 2]; v1.z = (y >= 0.f) ? y : SLOPE * y;
    y = v1.w * sc[c1 + 3] + bi[c1 + 3]; v1.w = (y >= 0.f) ? y : SLOPE * y;

    o4[i0]       = v0;
    o4[i0 + 256] = v1;
}

// ---------------------------------------------------------------------------
// Launch
// inputs (metadata order): feats f32[N_IN*64], W f32[27*64*64], gamma f32[64],
//   beta f32[64], in_map i32[27*M], out_map i32[27*M], num_out i32[1]
// ---------------------------------------------------------------------------
extern "C" void kernel_launch(void* const* d_in, const int* in_sizes, int n_in,
                              void* d_out, int out_size)
{
    const float* feats   = (const float*)d_in[0];
    const float* W       = (const float*)d_in[1];
    const float* gamma   = (const float*)d_in[2];
    const float* beta    = (const float*)d_in[3];
    const int*   in_map  = (const int*)d_in[4];
    const int*   out_map = (const int*)d_in[5];
    float*       out     = (float*)d_out;

    precvt_kernel<<<8192, 256>>>(feats, W, reinterpret_cast<float4*>(out));

    cudaFuncSetAttribute(conv_kernel,
                         cudaFuncAttributeMaxDynamicSharedMemorySize,
                         SMEM_BYTES);
    dim3 grid(MPAIR / BLK_PAIRS, KOFF);          // 64 x 27
    conv_kernel<<<grid, 256, SMEM_BYTES>>>(in_map, out_map, out);

    stats_kernel<<<512, 256>>>(reinterpret_cast<const float4*>(out));

    apply_kernel<<<8192, 256>>>(out, gamma, beta);
}

// round 13
// speedup vs baseline: 1.0819x; 1.0458x over previous
#include <cuda_runtime.h>
#include <cuda_fp16.h>
#include <cstdint>

// Problem constants (fixed by the reference)
#define CIN   64
#define COUT  64
#define KOFF  27
#define MPAIR 131072
#define NOUT  262144
#define NIN   262144
#define EPS   1e-5f
#define SLOPE 0.01f

// conv tiling: block = 256 threads (8 warps); warp = 8 pairs/step;
// block = 64 pairs/step x 32 steps = 2048 pairs. grid = (64, 27).
#define BLK_PAIRS 2048
#define STEPS     32

// smem: two staging buffers of 64 rows x 68 floats (272B row stride)
#define BUF_STRIDE 68
#define BUF_ROWS   64
#define BUF_FLOATS (BUF_ROWS * BUF_STRIDE)
#define SMEM_BYTES (2 * BUF_FLOATS * 4)     // 34816

// Pre-converted fp16 operands (device scratch; no runtime allocation)
// feats row layout (32 uints = 64 fp16): uint index p = a*8 + kt*2 + h
// holds half2( feats[ci], feats[ci+1] ), ci = kt*16 + 2a + 8h.
__device__ uint32_t g_featsH[NIN * 32];          // 33.5 MB
// W fragments per k: lane-major, lane (r,a) owns 64 uints:
// index mt*16 + kt*4 + j, j bit0 = cout+8, bit1 = cin+8:
//   half2( W[ci][co], W[ci+1][co] ), ci = 16kt+2a+8*(j>>1), co = 16mt+r+8*(j&1)
__device__ uint32_t g_WH[KOFF * 2048];           // 216 KB

// BN statistics scratch
__device__ float g_sum[COUT];
__device__ float g_sumsq[COUT];

__device__ __forceinline__ uint32_t smem_u32(const void* p) {
    uint32_t a;
    asm("{ .reg .u64 t; cvta.to.shared.u64 t, %1; cvt.u32.u64 %0, t; }"
        : "=r"(a) : "l"(p));
    return a;
}

// ---------------------------------------------------------------------------
// Kernel 0: fused zero(out) + pre-convert feats/W to fp16 fragment layouts.
// grid = 8192 x 256.
// ---------------------------------------------------------------------------
__global__ void __launch_bounds__(256)
precvt_kernel(const float* __restrict__ feats, const float* __restrict__ W,
              float4* __restrict__ out4)
{
    const int tid = threadIdx.x;
    const int t4  = blockIdx.x * 256 + tid;        // 0 .. 2,097,151

    // zero the 67 MB accumulator (2 float4s per thread)
    const float4 z = make_float4(0.f, 0.f, 0.f, 0.f);
    out4[2 * (size_t)t4]     = z;
    out4[2 * (size_t)t4 + 1] = z;
    if (blockIdx.x == 0 && tid < COUT) {
        g_sum[tid]   = 0.f;
        g_sumsq[tid] = 0.f;
    }

    // feats packing (B-fragment layout)
    const int row = t4 >> 3;
    const int p0  = (t4 & 7) << 2;                 // first of 4 uint slots
    const float* src = feats + (size_t)row * CIN;
    uint32_t v[4];
    #pragma unroll
    for (int i = 0; i < 4; i++) {
        const int up = p0 + i;
        const int a  = up >> 3;
        const int kt = (up >> 1) & 3;
        const int h  = up & 1;
        const int ci = kt * 16 + 2 * a + 8 * h;
        __half2 hv = __floats2half2_rn(src[ci], src[ci + 1]);
        v[i] = *reinterpret_cast<uint32_t*>(&hv);
    }
    *reinterpret_cast<uint4*>(g_featsH + (size_t)row * 32 + p0) =
        make_uint4(v[0], v[1], v[2], v[3]);

    // W packing (A-fragment, lane-stationary layout)
    if (blockIdx.x < KOFF) {
        const float* Wk = W + blockIdx.x * (CIN * COUT);
        uint32_t* dst = g_WH + blockIdx.x * 2048;
        for (int i = tid; i < 2048; i += 256) {
            const int lane = i >> 6;
            const int rem  = i & 63;
            const int mt   = rem >> 4;
            const int kt   = (rem >> 2) & 3;
            const int j    = rem & 3;
            const int r    = lane >> 2;
            const int a    = lane & 3;
            const int ci   = 16 * kt + 2 * a + 8 * (j >> 1);
            const int co   = 16 * mt + r + 8 * (j & 1);
            __half2 hv = __floats2half2_rn(Wk[ci * COUT + co],
                                           Wk[(ci + 1) * COUT + co]);
            dst[i] = *reinterpret_cast<uint32_t*>(&hv);
        }
    }
}

// ---------------------------------------------------------------------------
// Kernel 1: sparse conv, register-stationary W (A operand), feats as B.
// D[cout=64, pair=8] per warp-step via 16x mma m16n8k16 (f32 acc).
// No LDS in the hot loop. Scatter via cp.reduce.async.bulk, double buffered.
// (R10-verified configuration: this loop sits on the measured LTS floor.)
// grid = (MPAIR/2048, KOFF); block = 256.
// ---------------------------------------------------------------------------
__global__ void __launch_bounds__(256, 2)
conv_kernel(const int* __restrict__ in_map,
            const int* __restrict__ out_map,
            float*     __restrict__ out)
{
    extern __shared__ float bufs[];

    const int k    = blockIdx.y;
    const int tid  = threadIdx.x;
    const int warp = tid >> 5;
    const int lane = tid & 31;
    const int r = lane >> 2;   // 0..7 (fragment group id)
    const int a = lane & 3;    // 0..3

    const int* im = in_map  + k * MPAIR;
    const int* om = out_map + k * MPAIR;

    // ---- stationary W fragments: 64 uints per lane, loaded once ----
    uint32_t Wf[64];
    {
        const uint4* wp = reinterpret_cast<const uint4*>(
            g_WH + k * 2048 + lane * 64);
        #pragma unroll
        for (int i = 0; i < 16; i++)
            *reinterpret_cast<uint4*>(Wf + 4 * i) = wp[i];
    }

    const int base_w = blockIdx.x * BLK_PAIRS + warp * 8;
    float* wbase = bufs + warp * 8 * BUF_STRIDE;

    // ---- prologue: gather step 0 ----
    uint32_t B0[8];
    int orow = 0;
    {
        const uint4* rp = reinterpret_cast<const uint4*>(
            g_featsH + (size_t)im[base_w + r] * 32 + a * 8);
        *reinterpret_cast<uint4*>(B0)     = rp[0];
        *reinterpret_cast<uint4*>(B0 + 4) = rp[1];
        if (lane < 8) orow = om[base_w + lane];
    }

    #pragma unroll 2
    for (int s = 0; s < STEPS; s++) {
        // ---- prefetch step s+1 ----
        uint32_t Bn[8];
        int orow_n = 0;
        if (s < STEPS - 1) {
            const int basen = base_w + (s + 1) * 64;
            if (lane < 8) orow_n = om[basen + lane];
            const uint4* rp = reinterpret_cast<const uint4*>(
                g_featsH + (size_t)im[basen + r] * 32 + a * 8);
            *reinterpret_cast<uint4*>(Bn)     = rp[0];
            *reinterpret_cast<uint4*>(Bn + 4) = rp[1];
        }

        // ---- MMA: D[64 cout, 8 pairs], K=64 ----
        float acc[4][4];
        #pragma unroll
        for (int mt = 0; mt < 4; mt++)
            #pragma unroll
            for (int q = 0; q < 4; q++) acc[mt][q] = 0.f;

        #pragma unroll
        for (int kt = 0; kt < 4; kt++) {
            const uint32_t b0 = B0[2 * kt];
            const uint32_t b1 = B0[2 * kt + 1];
            #pragma unroll
            for (int mt = 0; mt < 4; mt++) {
                const uint32_t* w = Wf + mt * 16 + kt * 4;
                asm volatile(
                    "mma.sync.aligned.m16n8k16.row.col.f32.f16.f16.f32 "
                    "{%0,%1,%2,%3}, {%4,%5,%6,%7}, {%8,%9}, {%0,%1,%2,%3};"
                    : "+f"(acc[mt][0]), "+f"(acc[mt][1]),
                      "+f"(acc[mt][2]), "+f"(acc[mt][3])
                    : "r"(w[0]), "r"(w[1]), "r"(w[2]), "r"(w[3]),
                      "r"(b0), "r"(b1));
            }
        }

        // ---- epilogue: stage 8 rows (pair-major), bulk reduce-add ----
        float* wbuf = wbase + (s & 1) * BUF_FLOATS;

        // the group that used THIS buffer (2 steps ago) must be read out
        asm volatile("cp.async.bulk.wait_group.read 1;" ::: "memory");
        __syncwarp();

        // D frag: lane(r,a), mt: c0=D[16mt+r][2a], c1=D[16mt+r][2a+1],
        //                        c2=D[16mt+r+8][2a], c3=D[16mt+r+8][2a+1]
        // staging row = pair (0..7), columns = cout
        #pragma unroll
        for (int mt = 0; mt < 4; mt++) {
            wbuf[(2 * a)     * BUF_STRIDE + 16 * mt + r]     = acc[mt][0];
            wbuf[(2 * a + 1) * BUF_STRIDE + 16 * mt + r]     = acc[mt][1];
            wbuf[(2 * a)     * BUF_STRIDE + 16 * mt + r + 8] = acc[mt][2];
            wbuf[(2 * a + 1) * BUF_STRIDE + 16 * mt + r + 8] = acc[mt][3];
        }
        __syncwarp();
        asm volatile("fence.proxy.async.shared::cta;" ::: "memory");

        if (lane < 8) {
            float* dst = out + (size_t)orow * COUT;
            uint32_t src = smem_u32(wbuf + lane * BUF_STRIDE);
            asm volatile(
                "cp.reduce.async.bulk.global.shared::cta.bulk_group.add.f32 "
                "[%0], [%1], %2;"
                :: "l"(dst), "r"(src), "r"(256) : "memory");
        }
        asm volatile("cp.async.bulk.commit_group;" ::: "memory");

        // rotate pipeline registers
        orow = orow_n;
        #pragma unroll
        for (int i = 0; i < 8; i++) B0[i] = Bn[i];
    }

    // all reduce writes must complete before kernel end
    asm volatile("cp.async.bulk.wait_group 0;" ::: "memory");
}

// ---------------------------------------------------------------------------
// Kernel 2: per-column sum / sumsq, float4 loads.
// grid = 512 blocks x 256 threads; 512 rows per block (32 per thread).
// ---------------------------------------------------------------------------
__global__ void stats_kernel(const float4* __restrict__ out4) {
    __shared__ float4 ssum[256], ssq[256];
    const int tid = threadIdx.x;
    const int c4  = tid & 15;
    const int q   = tid >> 4;
    const int rowbase = blockIdx.x * 512;

    float4 s  = make_float4(0.f, 0.f, 0.f, 0.f);
    float4 s2 = make_float4(0.f, 0.f, 0.f, 0.f);
    #pragma unroll 8
    for (int i = 0; i < 32; i++) {
        const float4 v = out4[(size_t)(rowbase + i * 16 + q) * 16 + c4];
        s.x += v.x; s.y += v.y; s.z += v.z; s.w += v.w;
        s2.x += v.x * v.x; s2.y += v.y * v.y;
        s2.z += v.z * v.z; s2.w += v.w * v.w;
    }
    ssum[tid] = s; ssq[tid] = s2;
    __syncthreads();
    if (q == 0) {
        float4 ts  = make_float4(0.f, 0.f, 0.f, 0.f);
        float4 ts2 = make_float4(0.f, 0.f, 0.f, 0.f);
        #pragma unroll
        for (int g = 0; g < 16; g++) {
            const float4 u  = ssum[g * 16 + c4];
            const float4 u2 = ssq[g * 16 + c4];
            ts.x += u.x; ts.y += u.y; ts.z += u.z; ts.w += u.w;
            ts2.x += u2.x; ts2.y += u2.y; ts2.z += u2.z; ts2.w += u2.w;
        }
        atomicAdd(&g_sum[c4 * 4 + 0], ts.x);
        atomicAdd(&g_sum[c4 * 4 + 1], ts.y);
        atomicAdd(&g_sum[c4 * 4 + 2], ts.z);
        atomicAdd(&g_sum[c4 * 4 + 3], ts.w);
        atomicAdd(&g_sumsq[c4 * 4 + 0], ts2.x);
        atomicAdd(&g_sumsq[c4 * 4 + 1], ts2.y);
        atomicAdd(&g_sumsq[c4 * 4 + 2], ts2.z);
        atomicAdd(&g_sumsq[c4 * 4 + 3], ts2.w);
    }
}

// ---------------------------------------------------------------------------
// Kernel 3: BN affine + LeakyReLU, in place, 2 independent float4 per thread
// for load-latency ILP. grid = 8192 x 256.
// ---------------------------------------------------------------------------
__global__ void apply_kernel(float* __restrict__ out,
                             const float* __restrict__ gamma,
                             const float* __restrict__ beta)
{
    __shared__ float sc[COUT], bi[COUT];
    const int tid = threadIdx.x;
    if (tid < COUT) {
        const float inv_n = 1.f / (float)NOUT;
        float mean = g_sum[tid] * inv_n;
        float var  = g_sumsq[tid] * inv_n - mean * mean;
        float s = gamma[tid] * rsqrtf(var + EPS);
        sc[tid] = s;
        bi[tid] = beta[tid] - mean * s;
    }
    __syncthreads();

    float4* o4 = reinterpret_cast<float4*>(out);
    const int i0 = blockIdx.x * 512 + tid;           // two float4s, 256 apart
    float4 v0 = o4[i0];
    float4 v1 = o4[i0 + 256];
    const int c0 = (i0 & 15) * 4;
    const int c1 = ((i0 + 256) & 15) * 4;

    float y;
    y = v0.x * sc[c0 + 0] + bi[c0 + 0]; v0.x = (y >= 0.f) ? y : SLOPE * y;
    y = v0.y * sc[c0 + 1] + bi[c0 + 1]; v0.y = (y >= 0.f) ? y : SLOPE * y;
    y = v0.z * sc[c0 + 2] + bi[c0 + 2]; v0.z = (y >= 0.f) ? y : SLOPE * y;
    y = v0.w * sc[c0 + 3] + bi[c0 + 3]; v0.w = (y >= 0.f) ? y : SLOPE * y;
    y = v1.x * sc[c1 + 0] + bi[c1 + 0]; v1.x = (y >= 0.f) ? y : SLOPE * y;
    y = v1.y * sc[c1 + 1] + bi[c1 + 1]; v1.y = (y >= 0.f) ? y : SLOPE * y;
    y = v1.z * sc[c1 + 2] + bi[c1 + 2]; v1.z = (y >= 0.f) ? y : SLOPE * y;
    y = v1.w * sc[c1 + 3] + bi[c1 + 3]; v1.w = (y >= 0.f) ? y : SLOPE * y;

    o4[i0]       = v0;
    o4[i0 + 256] = v1;
}

// ---------------------------------------------------------------------------
// Launch
// inputs (metadata order): feats f32[N_IN*64], W f32[27*64*64], gamma f32[64],
//   beta f32[64], in_map i32[27*M], out_map i32[27*M], num_out i32[1]
// ---------------------------------------------------------------------------
extern "C" void kernel_launch(void* const* d_in, const int* in_sizes, int n_in,
                              void* d_out, int out_size)
{
    const float* feats   = (const float*)d_in[0];
    const float* W       = (const float*)d_in[1];
    const float* gamma   = (const float*)d_in[2];
    const float* beta    = (const float*)d_in[3];
    const int*   in_map  = (const int*)d_in[4];
    const int*   out_map = (const int*)d_in[5];
    float*       out     = (float*)d_out;

    precvt_kernel<<<8192, 256>>>(feats, W, reinterpret_cast<float4*>(out));

    cudaFuncSetAttribute(conv_kernel,
                         cudaFuncAttributeMaxDynamicSharedMemorySize,
                         SMEM_BYTES);
    dim3 grid(MPAIR / BLK_PAIRS, KOFF);          // 64 x 27
    conv_kernel<<<grid, 256, SMEM_BYTES>>>(in_map, out_map, out);

    stats_kernel<<<512, 256>>>(reinterpret_cast<const float4*>(out));

    apply_kernel<<<8192, 256>>>(out, gamma, beta);
}

// round 14
// speedup vs baseline: 1.0967x; 1.0137x over previous
#include <cuda_runtime.h>
#include <cuda_fp16.h>
#include <cstdint>

// Problem constants (fixed by the reference)
#define CIN   64
#define COUT  64
#define KOFF  27
#define MPAIR 131072
#define NOUT  262144
#define NIN   262144
#define EPS   1e-5f
#define SLOPE 0.01f

// conv tiling: block = 256 threads (8 warps); warp = 8 pairs/step;
// block = 64 pairs/step x 32 steps = 2048 pairs. grid = (64, 27).
#define BLK_PAIRS 2048
#define STEPS     32

// smem: two staging buffers of 64 rows x 68 floats (272B row stride)
#define BUF_STRIDE 68
#define BUF_ROWS   64
#define BUF_FLOATS (BUF_ROWS * BUF_STRIDE)
#define SMEM_BYTES (2 * BUF_FLOATS * 4)     // 34816

// fused BN kernel geometry
#define BN_BLOCKS  296                      // 148 SMs x 2, all wave-1 resident
#define N_F4       4194304                  // NOUT*COUT/4
#define BN_STRIDE  (BN_BLOCKS * 256)        // 75776 (== 0 mod 16)

// Pre-converted fp16 operands (device scratch; no runtime allocation)
// feats row layout (32 uints = 64 fp16): uint index p = a*8 + kt*2 + h
// holds half2( feats[ci], feats[ci+1] ), ci = kt*16 + 2a + 8h.
__device__ uint32_t g_featsH[NIN * 32];          // 33.5 MB
// W fragments per k: lane-major, lane (r,a) owns 64 uints:
// index mt*16 + kt*4 + j, j bit0 = cout+8, bit1 = cin+8:
//   half2( W[ci][co], W[ci+1][co] ), ci = 16kt+2a+8*(j>>1), co = 16mt+r+8*(j&1)
__device__ uint32_t g_WH[KOFF * 2048];           // 216 KB

// BN statistics scratch + grid barrier counter
__device__ float g_sum[COUT];
__device__ float g_sumsq[COUT];
__device__ int   g_count;

__device__ __forceinline__ uint32_t smem_u32(const void* p) {
    uint32_t a;
    asm("{ .reg .u64 t; cvta.to.shared.u64 t, %1; cvt.u32.u64 %0, t; }"
        : "=r"(a) : "l"(p));
    return a;
}

// ---------------------------------------------------------------------------
// Kernel 0: fused zero(out) + pre-convert feats/W to fp16 fragment layouts.
// grid = 8192 x 256.
// ---------------------------------------------------------------------------
__global__ void __launch_bounds__(256)
precvt_kernel(const float* __restrict__ feats, const float* __restrict__ W,
              float4* __restrict__ out4)
{
    const int tid = threadIdx.x;
    const int t4  = blockIdx.x * 256 + tid;        // 0 .. 2,097,151

    // zero the 67 MB accumulator (2 float4s per thread)
    const float4 z = make_float4(0.f, 0.f, 0.f, 0.f);
    out4[2 * (size_t)t4]     = z;
    out4[2 * (size_t)t4 + 1] = z;
    if (blockIdx.x == 0 && tid < COUT) {
        g_sum[tid]   = 0.f;
        g_sumsq[tid] = 0.f;
        if (tid == 0) g_count = 0;
    }

    // feats packing (B-fragment layout)
    const int row = t4 >> 3;
    const int p0  = (t4 & 7) << 2;                 // first of 4 uint slots
    const float* src = feats + (size_t)row * CIN;
    uint32_t v[4];
    #pragma unroll
    for (int i = 0; i < 4; i++) {
        const int up = p0 + i;
        const int a  = up >> 3;
        const int kt = (up >> 1) & 3;
        const int h  = up & 1;
        const int ci = kt * 16 + 2 * a + 8 * h;
        __half2 hv = __floats2half2_rn(src[ci], src[ci + 1]);
        v[i] = *reinterpret_cast<uint32_t*>(&hv);
    }
    *reinterpret_cast<uint4*>(g_featsH + (size_t)row * 32 + p0) =
        make_uint4(v[0], v[1], v[2], v[3]);

    // W packing (A-fragment, lane-stationary layout)
    if (blockIdx.x < KOFF) {
        const float* Wk = W + blockIdx.x * (CIN * COUT);
        uint32_t* dst = g_WH + blockIdx.x * 2048;
        for (int i = tid; i < 2048; i += 256) {
            const int lane = i >> 6;
            const int rem  = i & 63;
            const int mt   = rem >> 4;
            const int kt   = (rem >> 2) & 3;
            const int j    = rem & 3;
            const int r    = lane >> 2;
            const int a    = lane & 3;
            const int ci   = 16 * kt + 2 * a + 8 * (j >> 1);
            const int co   = 16 * mt + r + 8 * (j & 1);
            __half2 hv = __floats2half2_rn(Wk[ci * COUT + co],
                                           Wk[(ci + 1) * COUT + co]);
            dst[i] = *reinterpret_cast<uint32_t*>(&hv);
        }
    }
}

// ---------------------------------------------------------------------------
// Kernel 1: sparse conv, register-stationary W (A operand), feats as B.
// D[cout=64, pair=8] per warp-step via 16x mma m16n8k16 (f32 acc).
// No LDS in the hot loop. Scatter via cp.reduce.async.bulk, double buffered.
// (R10/R13-verified configuration: sits on the measured LTS floor.)
// grid = (MPAIR/2048, KOFF); block = 256.
// ---------------------------------------------------------------------------
__global__ void __launch_bounds__(256, 2)
conv_kernel(const int* __restrict__ in_map,
            const int* __restrict__ out_map,
            float*     __restrict__ out)
{
    extern __shared__ float bufs[];

    const int k    = blockIdx.y;
    const int tid  = threadIdx.x;
    const int warp = tid >> 5;
    const int lane = tid & 31;
    const int r = lane >> 2;   // 0..7 (fragment group id)
    const int a = lane & 3;    // 0..3

    const int* im = in_map  + k * MPAIR;
    const int* om = out_map + k * MPAIR;

    // ---- stationary W fragments: 64 uints per lane, loaded once ----
    uint32_t Wf[64];
    {
        const uint4* wp = reinterpret_cast<const uint4*>(
            g_WH + k * 2048 + lane * 64);
        #pragma unroll
        for (int i = 0; i < 16; i++)
            *reinterpret_cast<uint4*>(Wf + 4 * i) = wp[i];
    }

    const int base_w = blockIdx.x * BLK_PAIRS + warp * 8;
    float* wbase = bufs + warp * 8 * BUF_STRIDE;

    // ---- prologue: gather step 0 ----
    uint32_t B0[8];
    int orow = 0;
    {
        const uint4* rp = reinterpret_cast<const uint4*>(
            g_featsH + (size_t)im[base_w + r] * 32 + a * 8);
        *reinterpret_cast<uint4*>(B0)     = rp[0];
        *reinterpret_cast<uint4*>(B0 + 4) = rp[1];
        if (lane < 8) orow = om[base_w + lane];
    }

    #pragma unroll 2
    for (int s = 0; s < STEPS; s++) {
        // ---- prefetch step s+1 ----
        uint32_t Bn[8];
        int orow_n = 0;
        if (s < STEPS - 1) {
            const int basen = base_w + (s + 1) * 64;
            if (lane < 8) orow_n = om[basen + lane];
            const uint4* rp = reinterpret_cast<const uint4*>(
                g_featsH + (size_t)im[basen + r] * 32 + a * 8);
            *reinterpret_cast<uint4*>(Bn)     = rp[0];
            *reinterpret_cast<uint4*>(Bn + 4) = rp[1];
        }

        // ---- MMA: D[64 cout, 8 pairs], K=64 ----
        float acc[4][4];
        #pragma unroll
        for (int mt = 0; mt < 4; mt++)
            #pragma unroll
            for (int q = 0; q < 4; q++) acc[mt][q] = 0.f;

        #pragma unroll
        for (int kt = 0; kt < 4; kt++) {
            const uint32_t b0 = B0[2 * kt];
            const uint32_t b1 = B0[2 * kt + 1];
            #pragma unroll
            for (int mt = 0; mt < 4; mt++) {
                const uint32_t* w = Wf + mt * 16 + kt * 4;
                asm volatile(
                    "mma.sync.aligned.m16n8k16.row.col.f32.f16.f16.f32 "
                    "{%0,%1,%2,%3}, {%4,%5,%6,%7}, {%8,%9}, {%0,%1,%2,%3};"
                    : "+f"(acc[mt][0]), "+f"(acc[mt][1]),
                      "+f"(acc[mt][2]), "+f"(acc[mt][3])
                    : "r"(w[0]), "r"(w[1]), "r"(w[2]), "r"(w[3]),
                      "r"(b0), "r"(b1));
            }
        }

        // ---- epilogue: stage 8 rows (pair-major), bulk reduce-add ----
        float* wbuf = wbase + (s & 1) * BUF_FLOATS;

        // the group that used THIS buffer (2 steps ago) must be read out
        asm volatile("cp.async.bulk.wait_group.read 1;" ::: "memory");
        __syncwarp();

        // D frag: lane(r,a), mt: c0=D[16mt+r][2a], c1=D[16mt+r][2a+1],
        //                        c2=D[16mt+r+8][2a], c3=D[16mt+r+8][2a+1]
        // staging row = pair (0..7), columns = cout
        #pragma unroll
        for (int mt = 0; mt < 4; mt++) {
            wbuf[(2 * a)     * BUF_STRIDE + 16 * mt + r]     = acc[mt][0];
            wbuf[(2 * a + 1) * BUF_STRIDE + 16 * mt + r]     = acc[mt][1];
            wbuf[(2 * a)     * BUF_STRIDE + 16 * mt + r + 8] = acc[mt][2];
            wbuf[(2 * a + 1) * BUF_STRIDE + 16 * mt + r + 8] = acc[mt][3];
        }
        __syncwarp();
        asm volatile("fence.proxy.async.shared::cta;" ::: "memory");

        if (lane < 8) {
            float* dst = out + (size_t)orow * COUT;
            uint32_t src = smem_u32(wbuf + lane * BUF_STRIDE);
            asm volatile(
                "cp.reduce.async.bulk.global.shared::cta.bulk_group.add.f32 "
                "[%0], [%1], %2;"
                :: "l"(dst), "r"(src), "r"(256) : "memory");
        }
        asm volatile("cp.async.bulk.commit_group;" ::: "memory");

        // rotate pipeline registers
        orow = orow_n;
        #pragma unroll
        for (int i = 0; i < 8; i++) B0[i] = Bn[i];
    }

    // all reduce writes must complete before kernel end
    asm volatile("cp.async.bulk.wait_group 0;" ::: "memory");
}

// ---------------------------------------------------------------------------
// Kernel 2: FUSED BatchNorm stats + affine + LeakyReLU, persistent.
// grid = 296 blocks x 256 threads — all resident in wave 1 (occupancy >= 2
// per SM is guaranteed: ~40 regs, 2KB smem), so the counter barrier is safe.
// Phase 1: grid-strided column sums (stride 75776 == 0 mod 16, so each
// thread's float4-column is invariant); block-reduce; atomicAdd.
// Barrier: threadfence + counter arrive + spin.
// Phase 2: read stats (L2-coherent via atomicAdd(..,0)), apply in place.
// ---------------------------------------------------------------------------
__global__ void __launch_bounds__(256)
bn_fused_kernel(float4* __restrict__ out4,
                const float* __restrict__ gamma,
                const float* __restrict__ beta)
{
    __shared__ float4 ssum[256], ssq[256];
    __shared__ float sc[COUT], bi[COUT];

    const int tid = threadIdx.x;
    const int gid = blockIdx.x * 256 + tid;
    const int c4  = tid & 15;
    const int q   = tid >> 4;

    // ---- phase 1: partial column sums over strided float4s ----
    float4 s  = make_float4(0.f, 0.f, 0.f, 0.f);
    float4 s2 = make_float4(0.f, 0.f, 0.f, 0.f);
    for (int idx = gid; idx < N_F4; idx += BN_STRIDE) {
        const float4 v = out4[idx];
        s.x += v.x; s.y += v.y; s.z += v.z; s.w += v.w;
        s2.x += v.x * v.x; s2.y += v.y * v.y;
        s2.z += v.z * v.z; s2.w += v.w * v.w;
    }
    ssum[tid] = s; ssq[tid] = s2;
    __syncthreads();
    if (q == 0) {
        // gid&15 == tid&15 == c4 for every strided idx, so lane-groups of
        // equal c4 hold the same float4-column; reduce the 16 groups.
        float4 ts  = make_float4(0.f, 0.f, 0.f, 0.f);
        float4 ts2 = make_float4(0.f, 0.f, 0.f, 0.f);
        #pragma unroll
        for (int g = 0; g < 16; g++) {
            const float4 u  = ssum[g * 16 + c4];
            const float4 u2 = ssq[g * 16 + c4];
            ts.x += u.x; ts.y += u.y; ts.z += u.z; ts.w += u.w;
            ts2.x += u2.x; ts2.y += u2.y; ts2.z += u2.z; ts2.w += u2.w;
        }
        atomicAdd(&g_sum[c4 * 4 + 0], ts.x);
        atomicAdd(&g_sum[c4 * 4 + 1], ts.y);
        atomicAdd(&g_sum[c4 * 4 + 2], ts.z);
        atomicAdd(&g_sum[c4 * 4 + 3], ts.w);
        atomicAdd(&g_sumsq[c4 * 4 + 0], ts2.x);
        atomicAdd(&g_sumsq[c4 * 4 + 1], ts2.y);
        atomicAdd(&g_sumsq[c4 * 4 + 2], ts2.z);
        atomicAdd(&g_sumsq[c4 * 4 + 3], ts2.w);
    }

    // ---- grid barrier ----
    if (tid == 0) {
        __threadfence();
        atomicAdd(&g_count, 1);
        while (atomicAdd(&g_count, 0) < BN_BLOCKS) { }
    }
    __syncthreads();

    // ---- phase 2: scale/bias then apply ----
    if (tid < COUT) {
        const float inv_n = 1.f / (float)NOUT;
        const float mean = atomicAdd(&g_sum[tid], 0.f) * inv_n;
        const float var  = atomicAdd(&g_sumsq[tid], 0.f) * inv_n - mean * mean;
        const float sg = gamma[tid] * rsqrtf(var + EPS);
        sc[tid] = sg;
        bi[tid] = beta[tid] - mean * sg;
    }
    __syncthreads();

    for (int idx = gid; idx < N_F4; idx += BN_STRIDE) {
        float4 v = out4[idx];
        const int c = c4 * 4;                 // idx&15 == c4 (stride mod 16)
        float y;
        y = v.x * sc[c + 0] + bi[c + 0]; v.x = (y >= 0.f) ? y : SLOPE * y;
        y = v.y * sc[c + 1] + bi[c + 1]; v.y = (y >= 0.f) ? y : SLOPE * y;
        y = v.z * sc[c + 2] + bi[c + 2]; v.z = (y >= 0.f) ? y : SLOPE * y;
        y = v.w * sc[c + 3] + bi[c + 3]; v.w = (y >= 0.f) ? y : SLOPE * y;
        out4[idx] = v;
    }
}

// ---------------------------------------------------------------------------
// Launch
// inputs (metadata order): feats f32[N_IN*64], W f32[27*64*64], gamma f32[64],
//   beta f32[64], in_map i32[27*M], out_map i32[27*M], num_out i32[1]
// ---------------------------------------------------------------------------
extern "C" void kernel_launch(void* const* d_in, const int* in_sizes, int n_in,
                              void* d_out, int out_size)
{
    const float* feats   = (const float*)d_in[0];
    const float* W       = (const float*)d_in[1];
    const float* gamma   = (const float*)d_in[2];
    const float* beta    = (const float*)d_in[3];
    const int*   in_map  = (const int*)d_in[4];
    const int*   out_map = (const int*)d_in[5];
    float*       out     = (float*)d_out;

    precvt_kernel<<<8192, 256>>>(feats, W, reinterpret_cast<float4*>(out));

    cudaFuncSetAttribute(conv_kernel,
                         cudaFuncAttributeMaxDynamicSharedMemorySize,
                         SMEM_BYTES);
    dim3 grid(MPAIR / BLK_PAIRS, KOFF);          // 64 x 27
    conv_kernel<<<grid, 256, SMEM_BYTES>>>(in_map, out_map, out);

    bn_fused_kernel<<<BN_BLOCKS, 256>>>(reinterpret_cast<float4*>(out),
                                        gamma, beta);
}

// round 15
// speedup vs baseline: 1.0968x; 1.0001x over previous
#include <cuda_runtime.h>
#include <cuda_fp16.h>
#include <cstdint>

// Problem constants (fixed by the reference)
#define CIN   64
#define COUT  64
#define KOFF  27
#define MPAIR 131072
#define NOUT  262144
#define NIN   262144
#define EPS   1e-5f
#define SLOPE 0.01f

// conv tiling: block = 256 threads (8 warps); warp = 8 pairs/step;
// block = 64 pairs/step x 32 steps = 2048 pairs. grid = (64, 27).
#define BLK_PAIRS 2048
#define STEPS     32

// smem: two staging buffers of 64 rows x 68 floats (272B row stride)
#define BUF_STRIDE 68
#define BUF_ROWS   64
#define BUF_FLOATS (BUF_ROWS * BUF_STRIDE)
#define SMEM_BYTES (2 * BUF_FLOATS * 4)     // 34816

// fused BN kernel geometry
#define BN_BLOCKS  296                      // 148 SMs x 2, all wave-1 resident
#define N_F4       4194304                  // NOUT*COUT/4
#define BN_STRIDE  (BN_BLOCKS * 256)        // 75776 (== 0 mod 16)

// Pre-converted fp16 operands (device scratch; no runtime allocation)
// feats row layout (32 uints = 64 fp16): uint index p = a*8 + kt*2 + h
// holds half2( feats[ci], feats[ci+1] ), ci = kt*16 + 2a + 8h.
__device__ uint32_t g_featsH[NIN * 32];          // 33.5 MB
// W fragments per k: lane-major, lane (r,a) owns 64 uints:
// index mt*16 + kt*4 + j, j bit0 = cout+8, bit1 = cin+8:
//   half2( W[ci][co], W[ci+1][co] ), ci = 16kt+2a+8*(j>>1), co = 16mt+r+8*(j&1)
__device__ uint32_t g_WH[KOFF * 2048];           // 216 KB

// BN statistics scratch + grid barrier counter
__device__ float g_sum[COUT];
__device__ float g_sumsq[COUT];
__device__ int   g_count;

__device__ __forceinline__ uint32_t smem_u32(const void* p) {
    uint32_t a;
    asm("{ .reg .u64 t; cvta.to.shared.u64 t, %1; cvt.u32.u64 %0, t; }"
        : "=r"(a) : "l"(p));
    return a;
}

// ---------------------------------------------------------------------------
// Kernel 0: fused zero(out) + pre-convert feats/W to fp16 fragment layouts.
// Coalesced: each block stages its 32 feats rows (8 KB) in smem via
// LDG.128s, then does the fragment permutation from smem (LDS is cheap,
// the global scatter-replay problem disappears). grid = 8192 x 256.
// ---------------------------------------------------------------------------
__global__ void __launch_bounds__(256)
precvt_kernel(const float* __restrict__ feats, const float* __restrict__ W,
              float4* __restrict__ out4)
{
    __shared__ float srows[32 * CIN];              // 8 KB: 32 feats rows

    const int tid = threadIdx.x;
    const int blk = blockIdx.x;
    const int t4  = blk * 256 + tid;               // 0 .. 2,097,151

    // coalesced stage of this block's 32 rows (512 float4s)
    {
        const float4* fsrc = reinterpret_cast<const float4*>(
            feats + (size_t)blk * 32 * CIN);
        float4* s4 = reinterpret_cast<float4*>(srows);
        s4[tid]       = fsrc[tid];
        s4[tid + 256] = fsrc[tid + 256];
    }

    // zero the 67 MB accumulator (2 float4s per thread)
    const float4 z = make_float4(0.f, 0.f, 0.f, 0.f);
    out4[2 * (size_t)t4]     = z;
    out4[2 * (size_t)t4 + 1] = z;
    if (blk == 0 && tid < COUT) {
        g_sum[tid]   = 0.f;
        g_sumsq[tid] = 0.f;
        if (tid == 0) g_count = 0;
    }
    __syncthreads();

    // feats packing (B-fragment layout) from smem
    const int rloc = tid >> 3;                     // local row 0..31
    const int p0   = (tid & 7) << 2;               // first of 4 uint slots
    const float* src = srows + rloc * CIN;
    uint32_t v[4];
    #pragma unroll
    for (int i = 0; i < 4; i++) {
        const int up = p0 + i;
        const int a  = up >> 3;
        const int kt = (up >> 1) & 3;
        const int h  = up & 1;
        const int ci = kt * 16 + 2 * a + 8 * h;
        __half2 hv = __floats2half2_rn(src[ci], src[ci + 1]);
        v[i] = *reinterpret_cast<uint32_t*>(&hv);
    }
    *reinterpret_cast<uint4*>(
        g_featsH + ((size_t)blk * 32 + rloc) * 32 + p0) =
        make_uint4(v[0], v[1], v[2], v[3]);

    // W packing (A-fragment, lane-stationary layout)
    if (blk < KOFF) {
        const float* Wk = W + blk * (CIN * COUT);
        uint32_t* dst = g_WH + blk * 2048;
        for (int i = tid; i < 2048; i += 256) {
            const int lane = i >> 6;
            const int rem  = i & 63;
            const int mt   = rem >> 4;
            const int kt   = (rem >> 2) & 3;
            const int j    = rem & 3;
            const int r    = lane >> 2;
            const int a    = lane & 3;
            const int ci   = 16 * kt + 2 * a + 8 * (j >> 1);
            const int co   = 16 * mt + r + 8 * (j & 1);
            __half2 hv = __floats2half2_rn(Wk[ci * COUT + co],
                                           Wk[(ci + 1) * COUT + co]);
            dst[i] = *reinterpret_cast<uint32_t*>(&hv);
        }
    }
}

// ---------------------------------------------------------------------------
// Kernel 1: sparse conv, register-stationary W (A operand), feats as B.
// D[cout=64, pair=8] per warp-step via 16x mma m16n8k16 (f32 acc).
// No LDS in the hot loop. Scatter via cp.reduce.async.bulk, double buffered.
// (R10/R13-verified configuration: sits on the measured LTS floor. FROZEN.)
// grid = (MPAIR/2048, KOFF); block = 256.
// ---------------------------------------------------------------------------
__global__ void __launch_bounds__(256, 2)
conv_kernel(const int* __restrict__ in_map,
            const int* __restrict__ out_map,
            float*     __restrict__ out)
{
    extern __shared__ float bufs[];

    const int k    = blockIdx.y;
    const int tid  = threadIdx.x;
    const int warp = tid >> 5;
    const int lane = tid & 31;
    const int r = lane >> 2;   // 0..7 (fragment group id)
    const int a = lane & 3;    // 0..3

    const int* im = in_map  + k * MPAIR;
    const int* om = out_map + k * MPAIR;

    // ---- stationary W fragments: 64 uints per lane, loaded once ----
    uint32_t Wf[64];
    {
        const uint4* wp = reinterpret_cast<const uint4*>(
            g_WH + k * 2048 + lane * 64);
        #pragma unroll
        for (int i = 0; i < 16; i++)
            *reinterpret_cast<uint4*>(Wf + 4 * i) = wp[i];
    }

    const int base_w = blockIdx.x * BLK_PAIRS + warp * 8;
    float* wbase = bufs + warp * 8 * BUF_STRIDE;

    // ---- prologue: gather step 0 ----
    uint32_t B0[8];
    int orow = 0;
    {
        const uint4* rp = reinterpret_cast<const uint4*>(
            g_featsH + (size_t)im[base_w + r] * 32 + a * 8);
        *reinterpret_cast<uint4*>(B0)     = rp[0];
        *reinterpret_cast<uint4*>(B0 + 4) = rp[1];
        if (lane < 8) orow = om[base_w + lane];
    }

    #pragma unroll 2
    for (int s = 0; s < STEPS; s++) {
        // ---- prefetch step s+1 ----
        uint32_t Bn[8];
        int orow_n = 0;
        if (s < STEPS - 1) {
            const int basen = base_w + (s + 1) * 64;
            if (lane < 8) orow_n = om[basen + lane];
            const uint4* rp = reinterpret_cast<const uint4*>(
                g_featsH + (size_t)im[basen + r] * 32 + a * 8);
            *reinterpret_cast<uint4*>(Bn)     = rp[0];
            *reinterpret_cast<uint4*>(Bn + 4) = rp[1];
        }

        // ---- MMA: D[64 cout, 8 pairs], K=64 ----
        float acc[4][4];
        #pragma unroll
        for (int mt = 0; mt < 4; mt++)
            #pragma unroll
            for (int q = 0; q < 4; q++) acc[mt][q] = 0.f;

        #pragma unroll
        for (int kt = 0; kt < 4; kt++) {
            const uint32_t b0 = B0[2 * kt];
            const uint32_t b1 = B0[2 * kt + 1];
            #pragma unroll
            for (int mt = 0; mt < 4; mt++) {
                const uint32_t* w = Wf + mt * 16 + kt * 4;
                asm volatile(
                    "mma.sync.aligned.m16n8k16.row.col.f32.f16.f16.f32 "
                    "{%0,%1,%2,%3}, {%4,%5,%6,%7}, {%8,%9}, {%0,%1,%2,%3};"
                    : "+f"(acc[mt][0]), "+f"(acc[mt][1]),
                      "+f"(acc[mt][2]), "+f"(acc[mt][3])
                    : "r"(w[0]), "r"(w[1]), "r"(w[2]), "r"(w[3]),
                      "r"(b0), "r"(b1));
            }
        }

        // ---- epilogue: stage 8 rows (pair-major), bulk reduce-add ----
        float* wbuf = wbase + (s & 1) * BUF_FLOATS;

        // the group that used THIS buffer (2 steps ago) must be read out
        asm volatile("cp.async.bulk.wait_group.read 1;" ::: "memory");
        __syncwarp();

        // D frag: lane(r,a), mt: c0=D[16mt+r][2a], c1=D[16mt+r][2a+1],
        //                        c2=D[16mt+r+8][2a], c3=D[16mt+r+8][2a+1]
        // staging row = pair (0..7), columns = cout
        #pragma unroll
        for (int mt = 0; mt < 4; mt++) {
            wbuf[(2 * a)     * BUF_STRIDE + 16 * mt + r]     = acc[mt][0];
            wbuf[(2 * a + 1) * BUF_STRIDE + 16 * mt + r]     = acc[mt][1];
            wbuf[(2 * a)     * BUF_STRIDE + 16 * mt + r + 8] = acc[mt][2];
            wbuf[(2 * a + 1) * BUF_STRIDE + 16 * mt + r + 8] = acc[mt][3];
        }
        __syncwarp();
        asm volatile("fence.proxy.async.shared::cta;" ::: "memory");

        if (lane < 8) {
            float* dst = out + (size_t)orow * COUT;
            uint32_t src = smem_u32(wbuf + lane * BUF_STRIDE);
            asm volatile(
                "cp.reduce.async.bulk.global.shared::cta.bulk_group.add.f32 "
                "[%0], [%1], %2;"
                :: "l"(dst), "r"(src), "r"(256) : "memory");
        }
        asm volatile("cp.async.bulk.commit_group;" ::: "memory");

        // rotate pipeline registers
        orow = orow_n;
        #pragma unroll
        for (int i = 0; i < 8; i++) B0[i] = Bn[i];
    }

    // all reduce writes must complete before kernel end
    asm volatile("cp.async.bulk.wait_group 0;" ::: "memory");
}

// ---------------------------------------------------------------------------
// Kernel 2: FUSED BatchNorm stats + affine + LeakyReLU, persistent.
// grid = 296 blocks x 256 threads — all resident in wave 1, so the counter
// barrier is safe. Phase 1: grid-strided column sums; block-reduce;
// atomicAdd. Barrier: threadfence + counter. Phase 2: apply in place.
// ---------------------------------------------------------------------------
__global__ void __launch_bounds__(256)
bn_fused_kernel(float4* __restrict__ out4,
                const float* __restrict__ gamma,
                const float* __restrict__ beta)
{
    __shared__ float4 ssum[256], ssq[256];
    __shared__ float sc[COUT], bi[COUT];

    const int tid = threadIdx.x;
    const int gid = blockIdx.x * 256 + tid;
    const int c4  = tid & 15;
    const int q   = tid >> 4;

    // ---- phase 1: partial column sums over strided float4s ----
    float4 s  = make_float4(0.f, 0.f, 0.f, 0.f);
    float4 s2 = make_float4(0.f, 0.f, 0.f, 0.f);
    for (int idx = gid; idx < N_F4; idx += BN_STRIDE) {
        const float4 v = out4[idx];
        s.x += v.x; s.y += v.y; s.z += v.z; s.w += v.w;
        s2.x += v.x * v.x; s2.y += v.y * v.y;
        s2.z += v.z * v.z; s2.w += v.w * v.w;
    }
    ssum[tid] = s; ssq[tid] = s2;
    __syncthreads();
    if (q == 0) {
        float4 ts  = make_float4(0.f, 0.f, 0.f, 0.f);
        float4 ts2 = make_float4(0.f, 0.f, 0.f, 0.f);
        #pragma unroll
        for (int g = 0; g < 16; g++) {
            const float4 u  = ssum[g * 16 + c4];
            const float4 u2 = ssq[g * 16 + c4];
            ts.x += u.x; ts.y += u.y; ts.z += u.z; ts.w += u.w;
            ts2.x += u2.x; ts2.y += u2.y; ts2.z += u2.z; ts2.w += u2.w;
        }
        atomicAdd(&g_sum[c4 * 4 + 0], ts.x);
        atomicAdd(&g_sum[c4 * 4 + 1], ts.y);
        atomicAdd(&g_sum[c4 * 4 + 2], ts.z);
        atomicAdd(&g_sum[c4 * 4 + 3], ts.w);
        atomicAdd(&g_sumsq[c4 * 4 + 0], ts2.x);
        atomicAdd(&g_sumsq[c4 * 4 + 1], ts2.y);
        atomicAdd(&g_sumsq[c4 * 4 + 2], ts2.z);
        atomicAdd(&g_sumsq[c4 * 4 + 3], ts2.w);
    }

    // ---- grid barrier ----
    if (tid == 0) {
        __threadfence();
        atomicAdd(&g_count, 1);
        while (atomicAdd(&g_count, 0) < BN_BLOCKS) { }
    }
    __syncthreads();

    // ---- phase 2: scale/bias then apply ----
    if (tid < COUT) {
        const float inv_n = 1.f / (float)NOUT;
        const float mean = atomicAdd(&g_sum[tid], 0.f) * inv_n;
        const float var  = atomicAdd(&g_sumsq[tid], 0.f) * inv_n - mean * mean;
        const float sg = gamma[tid] * rsqrtf(var + EPS);
        sc[tid] = sg;
        bi[tid] = beta[tid] - mean * sg;
    }
    __syncthreads();

    for (int idx = gid; idx < N_F4; idx += BN_STRIDE) {
        float4 v = out4[idx];
        const int c = c4 * 4;                 // idx&15 == c4 (stride mod 16)
        float y;
        y = v.x * sc[c + 0] + bi[c + 0]; v.x = (y >= 0.f) ? y : SLOPE * y;
        y = v.y * sc[c + 1] + bi[c + 1]; v.y = (y >= 0.f) ? y : SLOPE * y;
        y = v.z * sc[c + 2] + bi[c + 2]; v.z = (y >= 0.f) ? y : SLOPE * y;
        y = v.w * sc[c + 3] + bi[c + 3]; v.w = (y >= 0.f) ? y : SLOPE * y;
        out4[idx] = v;
    }
}

// ---------------------------------------------------------------------------
// Launch
// inputs (metadata order): feats f32[N_IN*64], W f32[27*64*64], gamma f32[64],
//   beta f32[64], in_map i32[27*M], out_map i32[27*M], num_out i32[1]
// ---------------------------------------------------------------------------
extern "C" void kernel_launch(void* const* d_in, const int* in_sizes, int n_in,
                              void* d_out, int out_size)
{
    const float* feats   = (const float*)d_in[0];
    const float* W       = (const float*)d_in[1];
    const float* gamma   = (const float*)d_in[2];
    const float* beta    = (const float*)d_in[3];
    const int*   in_map  = (const int*)d_in[4];
    const int*   out_map = (const int*)d_in[5];
    float*       out     = (float*)d_out;

    precvt_kernel<<<8192, 256>>>(feats, W, reinterpret_cast<float4*>(out));

    cudaFuncSetAttribute(conv_kernel,
                         cudaFuncAttributeMaxDynamicSharedMemorySize,
                         SMEM_BYTES);
    dim3 grid(MPAIR / BLK_PAIRS, KOFF);          // 64 x 27
    conv_kernel<<<grid, 256, SMEM_BYTES>>>(in_map, out_map, out);

    bn_fused_kernel<<<BN_BLOCKS, 256>>>(reinterpret_cast<float4*>(out),
                                        gamma, beta);
}

// round 16
// speedup vs baseline: 1.1069x; 1.0093x over previous
#include <cuda_runtime.h>
#include <cuda_fp16.h>
#include <cstdint>

// Problem constants (fixed by the reference)
#define CIN   64
#define COUT  64
#define KOFF  27
#define MPAIR 131072
#define NOUT  262144
#define NIN   262144
#define EPS   1e-5f
#define SLOPE 0.01f

// conv tiling: block = 256 threads (8 warps); warp = 8 pairs/step;
// block = 64 pairs/step x 32 steps = 2048 pairs. grid = (64, 27).
#define BLK_PAIRS 2048
#define STEPS     32

// smem: two staging buffers of 64 rows x 68 floats (272B row stride)
#define BUF_STRIDE 68
#define BUF_ROWS   64
#define BUF_FLOATS (BUF_ROWS * BUF_STRIDE)
#define SMEM_BYTES (2 * BUF_FLOATS * 4)     // 34816

// fused BN kernel geometry
#define BN_BLOCKS  296                      // 148 SMs x 2, all wave-1 resident
#define N_F4       4194304                  // NOUT*COUT/4
#define BN_STRIDE  (BN_BLOCKS * 256)        // 75776 (== 0 mod 16)

// Pre-converted fp16 operands (device scratch; no runtime allocation)
// feats row layout (32 uints = 64 fp16): uint index p = a*8 + kt*2 + h
// holds half2( feats[ci], feats[ci+1] ), ci = kt*16 + 2a + 8h.
__device__ uint32_t g_featsH[NIN * 32];          // 33.5 MB
// W fragments per k: lane-major, lane (r,a) owns 64 uints:
// index mt*16 + kt*4 + j, j bit0 = cout+8, bit1 = cin+8:
//   half2( W[ci][co], W[ci+1][co] ), ci = 16kt+2a+8*(j>>1), co = 16mt+r+8*(j&1)
__device__ uint32_t g_WH[KOFF * 2048];           // 216 KB

// BN statistics scratch + grid barrier counter
__device__ float g_sum[COUT];
__device__ float g_sumsq[COUT];
__device__ int   g_count;

__device__ __forceinline__ uint32_t smem_u32(const void* p) {
    uint32_t a;
    asm("{ .reg .u64 t; cvta.to.shared.u64 t, %1; cvt.u32.u64 %0, t; }"
        : "=r"(a) : "l"(p));
    return a;
}

// ---------------------------------------------------------------------------
// Kernel 0: fused zero(out) + pre-convert feats/W to fp16 fragment layouts.
// Coalesced: smem-staged feats rows; zero-stores are per-instruction
// contiguous (tid-indexed, not 2*t4-indexed) so each STG wavefront is full.
// grid = 8192 x 256.
// ---------------------------------------------------------------------------
__global__ void __launch_bounds__(256)
precvt_kernel(const float* __restrict__ feats, const float* __restrict__ W,
              float4* __restrict__ out4)
{
    __shared__ float srows[32 * CIN];              // 8 KB: 32 feats rows

    const int tid = threadIdx.x;
    const int blk = blockIdx.x;

    // coalesced stage of this block's 32 rows (512 float4s)
    {
        const float4* fsrc = reinterpret_cast<const float4*>(
            feats + (size_t)blk * 32 * CIN);
        float4* s4 = reinterpret_cast<float4*>(srows);
        s4[tid]       = fsrc[tid];
        s4[tid + 256] = fsrc[tid + 256];
    }

    // zero the 67 MB accumulator: 2 fully-coalesced float4 stores/thread
    const float4 z = make_float4(0.f, 0.f, 0.f, 0.f);
    const size_t zbase = (size_t)blk * 512;
    out4[zbase + tid]       = z;
    out4[zbase + 256 + tid] = z;
    if (blk == 0 && tid < COUT) {
        g_sum[tid]   = 0.f;
        g_sumsq[tid] = 0.f;
        if (tid == 0) g_count = 0;
    }
    __syncthreads();

    // feats packing (B-fragment layout) from smem
    const int rloc = tid >> 3;                     // local row 0..31
    const int p0   = (tid & 7) << 2;               // first of 4 uint slots
    const float* src = srows + rloc * CIN;
    uint32_t v[4];
    #pragma unroll
    for (int i = 0; i < 4; i++) {
        const int up = p0 + i;
        const int a  = up >> 3;
        const int kt = (up >> 1) & 3;
        const int h  = up & 1;
        const int ci = kt * 16 + 2 * a + 8 * h;
        __half2 hv = __floats2half2_rn(src[ci], src[ci + 1]);
        v[i] = *reinterpret_cast<uint32_t*>(&hv);
    }
    *reinterpret_cast<uint4*>(
        g_featsH + ((size_t)blk * 32 + rloc) * 32 + p0) =
        make_uint4(v[0], v[1], v[2], v[3]);

    // W packing (A-fragment, lane-stationary layout)
    if (blk < KOFF) {
        const float* Wk = W + blk * (CIN * COUT);
        uint32_t* dst = g_WH + blk * 2048;
        for (int i = tid; i < 2048; i += 256) {
            const int lane = i >> 6;
            const int rem  = i & 63;
            const int mt   = rem >> 4;
            const int kt   = (rem >> 2) & 3;
            const int j    = rem & 3;
            const int r    = lane >> 2;
            const int a    = lane & 3;
            const int ci   = 16 * kt + 2 * a + 8 * (j >> 1);
            const int co   = 16 * mt + r + 8 * (j & 1);
            __half2 hv = __floats2half2_rn(Wk[ci * COUT + co],
                                           Wk[(ci + 1) * COUT + co]);
            dst[i] = *reinterpret_cast<uint32_t*>(&hv);
        }
    }
}

// ---------------------------------------------------------------------------
// Kernel 1: sparse conv, register-stationary W (A operand), feats as B.
// D[cout=64, pair=8] per warp-step via 16x mma m16n8k16 (f32 acc).
// No LDS in the hot loop. Scatter via cp.reduce.async.bulk, double buffered.
// (R10/R13-verified configuration: sits on the measured LTS floor. FROZEN.)
// grid = (MPAIR/2048, KOFF); block = 256.
// ---------------------------------------------------------------------------
__global__ void __launch_bounds__(256, 2)
conv_kernel(const int* __restrict__ in_map,
            const int* __restrict__ out_map,
            float*     __restrict__ out)
{
    extern __shared__ float bufs[];

    const int k    = blockIdx.y;
    const int tid  = threadIdx.x;
    const int warp = tid >> 5;
    const int lane = tid & 31;
    const int r = lane >> 2;   // 0..7 (fragment group id)
    const int a = lane & 3;    // 0..3

    const int* im = in_map  + k * MPAIR;
    const int* om = out_map + k * MPAIR;

    // ---- stationary W fragments: 64 uints per lane, loaded once ----
    uint32_t Wf[64];
    {
        const uint4* wp = reinterpret_cast<const uint4*>(
            g_WH + k * 2048 + lane * 64);
        #pragma unroll
        for (int i = 0; i < 16; i++)
            *reinterpret_cast<uint4*>(Wf + 4 * i) = wp[i];
    }

    const int base_w = blockIdx.x * BLK_PAIRS + warp * 8;
    float* wbase = bufs + warp * 8 * BUF_STRIDE;

    // ---- prologue: gather step 0 ----
    uint32_t B0[8];
    int orow = 0;
    {
        const uint4* rp = reinterpret_cast<const uint4*>(
            g_featsH + (size_t)im[base_w + r] * 32 + a * 8);
        *reinterpret_cast<uint4*>(B0)     = rp[0];
        *reinterpret_cast<uint4*>(B0 + 4) = rp[1];
        if (lane < 8) orow = om[base_w + lane];
    }

    #pragma unroll 2
    for (int s = 0; s < STEPS; s++) {
        // ---- prefetch step s+1 ----
        uint32_t Bn[8];
        int orow_n = 0;
        if (s < STEPS - 1) {
            const int basen = base_w + (s + 1) * 64;
            if (lane < 8) orow_n = om[basen + lane];
            const uint4* rp = reinterpret_cast<const uint4*>(
                g_featsH + (size_t)im[basen + r] * 32 + a * 8);
            *reinterpret_cast<uint4*>(Bn)     = rp[0];
            *reinterpret_cast<uint4*>(Bn + 4) = rp[1];
        }

        // ---- MMA: D[64 cout, 8 pairs], K=64 ----
        float acc[4][4];
        #pragma unroll
        for (int mt = 0; mt < 4; mt++)
            #pragma unroll
            for (int q = 0; q < 4; q++) acc[mt][q] = 0.f;

        #pragma unroll
        for (int kt = 0; kt < 4; kt++) {
            const uint32_t b0 = B0[2 * kt];
            const uint32_t b1 = B0[2 * kt + 1];
            #pragma unroll
            for (int mt = 0; mt < 4; mt++) {
                const uint32_t* w = Wf + mt * 16 + kt * 4;
                asm volatile(
                    "mma.sync.aligned.m16n8k16.row.col.f32.f16.f16.f32 "
                    "{%0,%1,%2,%3}, {%4,%5,%6,%7}, {%8,%9}, {%0,%1,%2,%3};"
                    : "+f"(acc[mt][0]), "+f"(acc[mt][1]),
                      "+f"(acc[mt][2]), "+f"(acc[mt][3])
                    : "r"(w[0]), "r"(w[1]), "r"(w[2]), "r"(w[3]),
                      "r"(b0), "r"(b1));
            }
        }

        // ---- epilogue: stage 8 rows (pair-major), bulk reduce-add ----
        float* wbuf = wbase + (s & 1) * BUF_FLOATS;

        // the group that used THIS buffer (2 steps ago) must be read out
        asm volatile("cp.async.bulk.wait_group.read 1;" ::: "memory");
        __syncwarp();

        // D frag: lane(r,a), mt: c0=D[16mt+r][2a], c1=D[16mt+r][2a+1],
        //                        c2=D[16mt+r+8][2a], c3=D[16mt+r+8][2a+1]
        // staging row = pair (0..7), columns = cout
        #pragma unroll
        for (int mt = 0; mt < 4; mt++) {
            wbuf[(2 * a)     * BUF_STRIDE + 16 * mt + r]     = acc[mt][0];
            wbuf[(2 * a + 1) * BUF_STRIDE + 16 * mt + r]     = acc[mt][1];
            wbuf[(2 * a)     * BUF_STRIDE + 16 * mt + r + 8] = acc[mt][2];
            wbuf[(2 * a + 1) * BUF_STRIDE + 16 * mt + r + 8] = acc[mt][3];
        }
        __syncwarp();
        asm volatile("fence.proxy.async.shared::cta;" ::: "memory");

        if (lane < 8) {
            float* dst = out + (size_t)orow * COUT;
            uint32_t src = smem_u32(wbuf + lane * BUF_STRIDE);
            asm volatile(
                "cp.reduce.async.bulk.global.shared::cta.bulk_group.add.f32 "
                "[%0], [%1], %2;"
                :: "l"(dst), "r"(src), "r"(256) : "memory");
        }
        asm volatile("cp.async.bulk.commit_group;" ::: "memory");

        // rotate pipeline registers
        orow = orow_n;
        #pragma unroll
        for (int i = 0; i < 8; i++) B0[i] = Bn[i];
    }

    // all reduce writes must complete before kernel end
    asm volatile("cp.async.bulk.wait_group 0;" ::: "memory");
}

// ---------------------------------------------------------------------------
// Kernel 2: FUSED BatchNorm stats + affine + LeakyReLU, persistent.
// grid = 296 blocks x 256 threads — all resident in wave 1, so the counter
// barrier is safe. Phase 1: grid-strided column sums (L1-bypass loads —
// pure stream; L2 keeps out resident for phase 2); block-reduce; atomicAdd.
// Barrier: threadfence + counter. Phase 2: apply in place.
// ---------------------------------------------------------------------------
__global__ void __launch_bounds__(256)
bn_fused_kernel(float4* __restrict__ out4,
                const float* __restrict__ gamma,
                const float* __restrict__ beta)
{
    __shared__ float4 ssum[256], ssq[256];
    __shared__ float sc[COUT], bi[COUT];

    const int tid = threadIdx.x;
    const int gid = blockIdx.x * 256 + tid;
    const int c4  = tid & 15;
    const int q   = tid >> 4;

    // ---- phase 1: partial column sums over strided float4s ----
    float4 s  = make_float4(0.f, 0.f, 0.f, 0.f);
    float4 s2 = make_float4(0.f, 0.f, 0.f, 0.f);
    for (int idx = gid; idx < N_F4; idx += BN_STRIDE) {
        const float4 v = __ldcg(out4 + idx);
        s.x += v.x; s.y += v.y; s.z += v.z; s.w += v.w;
        s2.x += v.x * v.x; s2.y += v.y * v.y;
        s2.z += v.z * v.z; s2.w += v.w * v.w;
    }
    ssum[tid] = s; ssq[tid] = s2;
    __syncthreads();
    if (q == 0) {
        float4 ts  = make_float4(0.f, 0.f, 0.f, 0.f);
        float4 ts2 = make_float4(0.f, 0.f, 0.f, 0.f);
        #pragma unroll
        for (int g = 0; g < 16; g++) {
            const float4 u  = ssum[g * 16 + c4];
            const float4 u2 = ssq[g * 16 + c4];
            ts.x += u.x; ts.y += u.y; ts.z += u.z; ts.w += u.w;
            ts2.x += u2.x; ts2.y += u2.y; ts2.z += u2.z; ts2.w += u2.w;
        }
        atomicAdd(&g_sum[c4 * 4 + 0], ts.x);
        atomicAdd(&g_sum[c4 * 4 + 1], ts.y);
        atomicAdd(&g_sum[c4 * 4 + 2], ts.z);
        atomicAdd(&g_sum[c4 * 4 + 3], ts.w);
        atomicAdd(&g_sumsq[c4 * 4 + 0], ts2.x);
        atomicAdd(&g_sumsq[c4 * 4 + 1], ts2.y);
        atomicAdd(&g_sumsq[c4 * 4 + 2], ts2.z);
        atomicAdd(&g_sumsq[c4 * 4 + 3], ts2.w);
    }

    // ---- grid barrier ----
    if (tid == 0) {
        __threadfence();
        atomicAdd(&g_count, 1);
        while (atomicAdd(&g_count, 0) < BN_BLOCKS) { }
    }
    __syncthreads();

    // ---- phase 2: scale/bias then apply ----
    if (tid < COUT) {
        const float inv_n = 1.f / (float)NOUT;
        const float mean = atomicAdd(&g_sum[tid], 0.f) * inv_n;
        const float var  = atomicAdd(&g_sumsq[tid], 0.f) * inv_n - mean * mean;
        const float sg = gamma[tid] * rsqrtf(var + EPS);
        sc[tid] = sg;
        bi[tid] = beta[tid] - mean * sg;
    }
    __syncthreads();

    for (int idx = gid; idx < N_F4; idx += BN_STRIDE) {
        float4 v = out4[idx];
        const int c = c4 * 4;                 // idx&15 == c4 (stride mod 16)
        float y;
        y = v.x * sc[c + 0] + bi[c + 0]; v.x = (y >= 0.f) ? y : SLOPE * y;
        y = v.y * sc[c + 1] + bi[c + 1]; v.y = (y >= 0.f) ? y : SLOPE * y;
        y = v.z * sc[c + 2] + bi[c + 2]; v.z = (y >= 0.f) ? y : SLOPE * y;
        y = v.w * sc[c + 3] + bi[c + 3]; v.w = (y >= 0.f) ? y : SLOPE * y;
        out4[idx] = v;
    }
}

// ---------------------------------------------------------------------------
// Launch
// inputs (metadata order): feats f32[N_IN*64], W f32[27*64*64], gamma f32[64],
//   beta f32[64], in_map i32[27*M], out_map i32[27*M], num_out i32[1]
// ---------------------------------------------------------------------------
extern "C" void kernel_launch(void* const* d_in, const int* in_sizes, int n_in,
                              void* d_out, int out_size)
{
    const float* feats   = (const float*)d_in[0];
    const float* W       = (const float*)d_in[1];
    const float* gamma   = (const float*)d_in[2];
    const float* beta    = (const float*)d_in[3];
    const int*   in_map  = (const int*)d_in[4];
    const int*   out_map = (const int*)d_in[5];
    float*       out     = (float*)d_out;

    precvt_kernel<<<8192, 256>>>(feats, W, reinterpret_cast<float4*>(out));

    cudaFuncSetAttribute(conv_kernel,
                         cudaFuncAttributeMaxDynamicSharedMemorySize,
                         SMEM_BYTES);
    dim3 grid(MPAIR / BLK_PAIRS, KOFF);          // 64 x 27
    conv_kernel<<<grid, 256, SMEM_BYTES>>>(in_map, out_map, out);

    bn_fused_kernel<<<BN_BLOCKS, 256>>>(reinterpret_cast<float4*>(out),
                                        gamma, beta);
}